// round 10
// baseline (speedup 1.0000x reference)
#include <cuda_runtime.h>
#include <cstdint>

// Distral multi-head tiny MLP (N = 32769 heads). R9 proved L2 persists across
// graph replays: protecting W1+b1 (52MB) with evict_last gave 24.6 -> 16.9us.
// R10 extends the resident set: W1+b1+x+b2 fully evict_last, plus 60% of W2
// lines via fractional policy (evict_last 0.6 / evict_first rest).
// Protected total ~91MB of 126MB L2. Steady-state DRAM ~28MB.
// float4 chunk-per-lane ownership, grid-strided, no smem/barriers.

#define HID 100
#define OUT 5

__device__ __forceinline__ uint64_t pol_keep() {
    uint64_t p;
    asm("createpolicy.fractional.L2::evict_last.b64 %0, 1.0;" : "=l"(p));
    return p;
}
__device__ __forceinline__ uint64_t pol_frac() {
    uint64_t p;
    // 60% of lines evict_last, remaining 40% evict_first (streaming)
    asm("createpolicy.fractional.L2::evict_last.L2::evict_first.b64 %0, 0.6;"
        : "=l"(p));
    return p;
}
__device__ __forceinline__ float4 ldg_hint(const float4* p, uint64_t pol) {
    float4 v;
    asm volatile("ld.global.nc.L2::cache_hint.v4.f32 {%0,%1,%2,%3}, [%4], %5;"
                 : "=f"(v.x), "=f"(v.y), "=f"(v.z), "=f"(v.w)
                 : "l"(p), "l"(pol));
    return v;
}
__device__ __forceinline__ float ldg_hint_f(const float* p, uint64_t pol) {
    float v;
    asm volatile("ld.global.nc.L2::cache_hint.f32 %0, [%1], %2;"
                 : "=f"(v) : "l"(p), "l"(pol));
    return v;
}

__global__ __launch_bounds__(256) void distral_kernel(
    const float* __restrict__ x,
    const float* __restrict__ W1,
    const float* __restrict__ b1,
    const float* __restrict__ W2,
    const float* __restrict__ b2,
    float* __restrict__ out,
    int n_heads)
{
    const int lane  = threadIdx.x & 31;
    const int gwarp = (blockIdx.x * blockDim.x + threadIdx.x) >> 5;
    const int nwarp = (gridDim.x * blockDim.x) >> 5;

    const uint64_t pk = pol_keep();   // W1, b1, x, b2: fully resident (54MB)
    const uint64_t pf = pol_frac();   // W2: 60% resident / 40% streaming

    // lane l (l<25) owns hidden units j in [4l, 4l+4)
    for (int head = gwarp; head < n_heads; head += nwarp) {
        const float4* g1 = (const float4*)(W1 + (size_t)head * (HID * 3));
        const float4* gb = (const float4*)(b1 + (size_t)head * HID);
        const float4* g2 = (const float4*)(W2 + (size_t)head * (OUT * HID));

        float4 w1a, w1b, w1c, b1v, w2v[OUT];
        if (lane < 25) {
            w1a = ldg_hint(g1 + 3 * lane + 0, pk);
            w1b = ldg_hint(g1 + 3 * lane + 1, pk);
            w1c = ldg_hint(g1 + 3 * lane + 2, pk);
            b1v = ldg_hint(gb + lane, pk);
            #pragma unroll
            for (int o = 0; o < OUT; o++) w2v[o] = ldg_hint(g2 + 25 * o + lane, pf);
        } else {
            w1a = w1b = w1c = b1v = make_float4(0.f, 0.f, 0.f, 0.f);
            #pragma unroll
            for (int o = 0; o < OUT; o++) w2v[o] = make_float4(0.f, 0.f, 0.f, 0.f);
        }

        const float x0 = ldg_hint_f(x + (size_t)head * 3 + 0, pk);
        const float x1 = ldg_hint_f(x + (size_t)head * 3 + 1, pk);
        const float x2 = ldg_hint_f(x + (size_t)head * 3 + 2, pk);

        const float f[12] = { w1a.x, w1a.y, w1a.z, w1a.w,
                              w1b.x, w1b.y, w1b.z, w1b.w,
                              w1c.x, w1c.y, w1c.z, w1c.w };
        const float bb[4] = { b1v.x, b1v.y, b1v.z, b1v.w };

        float h[4];
        #pragma unroll
        for (int k = 0; k < 4; k++) {
            float v = fmaf(f[3 * k + 0], x0,
                      fmaf(f[3 * k + 1], x1,
                      fmaf(f[3 * k + 2], x2, bb[k])));
            h[k] = fmaxf(v, 0.0f);
        }

        float logits[OUT];
        #pragma unroll
        for (int o = 0; o < OUT; o++) {
            float4 q = w2v[o];
            float p = fmaf(q.x, h[0], fmaf(q.y, h[1], fmaf(q.z, h[2], q.w * h[3])));
            #pragma unroll
            for (int s = 16; s; s >>= 1)
                p += __shfl_xor_sync(0xffffffffu, p, s);
            logits[o] = p + ldg_hint_f(b2 + (size_t)head * OUT + o, pk);
        }

        float mx = logits[0];
        #pragma unroll
        for (int o = 1; o < OUT; o++) mx = fmaxf(mx, logits[o]);
        float e[OUT], sum = 0.0f;
        #pragma unroll
        for (int o = 0; o < OUT; o++) { e[o] = __expf(logits[o] - mx); sum += e[o]; }
        float inv = __frcp_rn(sum);

        if (lane < OUT)
            out[(size_t)head * OUT + lane] = e[lane] * inv;
    }
}

extern "C" void kernel_launch(void* const* d_in, const int* in_sizes, int n_in,
                              void* d_out, int out_size)
{
    const float* x  = (const float*)d_in[0];
    const float* W1 = (const float*)d_in[1];
    const float* b1 = (const float*)d_in[2];
    const float* W2 = (const float*)d_in[3];
    const float* b2 = (const float*)d_in[4];
    float* out = (float*)d_out;

    const int n_heads = in_sizes[0] / 3;   // x is (N, 3)

    const int blocks = 148 * 6;            // L2-hit regime is latency-bound: keep warps up
    distral_kernel<<<blocks, 256>>>(x, W1, b1, W2, b2, out, n_heads);
}